// round 12
// baseline (speedup 1.0000x reference)
#include <cuda_runtime.h>
#include <cuda_bf16.h>
#include <mma.h>
#include <math.h>

using namespace nvcuda;

// Problem constants
#define D_MODEL 1024
#define NHEAD   16
#define DKH     64
#define S_LEN   2048
#define BATCH   4
#define ROWS    (BATCH * S_LEN)   // 8192

// Scratch (static device globals: allocation-free per harness rules)
__device__ float g_Q[ROWS * D_MODEL];
__device__ float g_K[ROWS * D_MODEL];
__device__ float g_V[ROWS * D_MODEL];
__device__ float g_ctx[ROWS * D_MODEL];

// ---------------------------------------------------------------------------
// fp32 -> (bf16 hi, bf16 lo) split helpers
// ---------------------------------------------------------------------------
__device__ __forceinline__ void split_store(__nv_bfloat16* hi, __nv_bfloat16* lo,
                                            int idx, float4 v)
{
    float f[4] = {v.x, v.y, v.z, v.w};
    __nv_bfloat16 h[4], l[4];
    #pragma unroll
    for (int e = 0; e < 4; e++) {
        h[e] = __float2bfloat16_rn(f[e]);
        l[e] = __float2bfloat16_rn(f[e] - __bfloat162float(h[e]));
    }
    *reinterpret_cast<__nv_bfloat162*>(hi + idx)     = __nv_bfloat162(h[0], h[1]);
    *reinterpret_cast<__nv_bfloat162*>(hi + idx + 2) = __nv_bfloat162(h[2], h[3]);
    *reinterpret_cast<__nv_bfloat162*>(lo + idx)     = __nv_bfloat162(l[0], l[1]);
    *reinterpret_cast<__nv_bfloat162*>(lo + idx + 2) = __nv_bfloat162(l[2], l[3]);
}

typedef wmma::fragment<wmma::matrix_a, 16,16,16, __nv_bfloat16, wmma::row_major> FragA;
typedef wmma::fragment<wmma::matrix_b, 16,16,16, __nv_bfloat16, wmma::col_major> FragBc;
typedef wmma::fragment<wmma::matrix_b, 16,16,16, __nv_bfloat16, wmma::row_major> FragBr;
typedef wmma::fragment<wmma::accumulator, 16,16,16, float> FragC;

// ---------------------------------------------------------------------------
// Projection GEMM, double-buffered:  C = A @ W^T + bias
// CTA 128x128, K-chunk 32, 8 warps (warp tile 32x64). Two smem buffers:
// store chunk k+1 overlaps MMA on chunk k; ONE barrier per chunk.
// ---------------------------------------------------------------------------
#define PBM 128
#define PBK 32
#define PP  40
#define PLANE_BYTES (PBM * PP * 2)       // 10240
#define BUF_BYTES   (4 * PLANE_BYTES)    // 40960 (Ahi,Alo,Bhi,Blo)
#define PSM_BYTES   (2 * BUF_BYTES)      // 81920 dynamic

__device__ __forceinline__ void proj_gemm_core(
    const float* __restrict__ A, const float* __restrict__ W,
    const float* __restrict__ bias, int m0, int n0,
    unsigned char* smem_raw, FragC (&acc)[2][4])
{
    const int K = D_MODEL;
    int tid = threadIdx.x;
    int wid = tid >> 5;
    int warp_m = wid & 3;
    int warp_n = wid >> 2;

    int lrow = tid >> 1;
    int lkh  = (tid & 1) * 16;
    const float* Ap = A + (size_t)(m0 + lrow) * K + lkh;
    const float* Wp = W + (size_t)(n0 + lrow) * K + lkh;

    float* btile = reinterpret_cast<float*>(smem_raw + BUF_BYTES);  // unions buf1

    // Prefetch chunk 0
    float4 ar[4], wr[4];
    #pragma unroll
    for (int j = 0; j < 4; j++) {
        ar[j] = *(const float4*)(Ap + j * 4);
        wr[j] = *(const float4*)(Wp + j * 4);
    }

    // Fill bias tile (in buf1 space) + store chunk 0 into buf0 (disjoint)
    for (int idx = tid; idx < 16 * 128; idx += 256) {
        int r = idx >> 7, c = idx & 127;
        btile[r * 136 + c] = bias[n0 + c];
    }
    {
        __nv_bfloat16* Ahi = reinterpret_cast<__nv_bfloat16*>(smem_raw);
        __nv_bfloat16* Alo = Ahi + PBM * PP;
        __nv_bfloat16* Bhi = Alo + PBM * PP;
        __nv_bfloat16* Blo = Bhi + PBM * PP;
        int sidx = lrow * PP + lkh;
        #pragma unroll
        for (int j = 0; j < 4; j++) {
            split_store(Ahi, Alo, sidx + j * 4, ar[j]);
            split_store(Bhi, Blo, sidx + j * 4, wr[j]);
        }
    }
    __syncthreads();

    // Init accumulators from bias tile
    #pragma unroll
    for (int mt = 0; mt < 2; mt++)
        #pragma unroll
        for (int nt = 0; nt < 4; nt++)
            wmma::load_matrix_sync(acc[mt][nt],
                btile + warp_n * 64 + nt * 16, 136, wmma::mem_row_major);

    // Prefetch chunk 1
    #pragma unroll
    for (int j = 0; j < 4; j++) {
        ar[j] = *(const float4*)(Ap + PBK + j * 4);
        wr[j] = *(const float4*)(Wp + PBK + j * 4);
    }
    __syncthreads();   // acc-frag loads done before buf1 (btile) is overwritten

    const int NCHUNK = K / PBK;   // 32
    for (int k = 0; k < NCHUNK; k++) {
        unsigned char* cur = smem_raw + (k & 1) * BUF_BYTES;
        unsigned char* nxt = smem_raw + ((k + 1) & 1) * BUF_BYTES;

        // Store chunk k+1 into other buffer (overlaps MMA below)
        if (k + 1 < NCHUNK) {
            __nv_bfloat16* nAhi = reinterpret_cast<__nv_bfloat16*>(nxt);
            __nv_bfloat16* nAlo = nAhi + PBM * PP;
            __nv_bfloat16* nBhi = nAlo + PBM * PP;
            __nv_bfloat16* nBlo = nBhi + PBM * PP;
            int sidx = lrow * PP + lkh;
            #pragma unroll
            for (int j = 0; j < 4; j++) {
                split_store(nAhi, nAlo, sidx + j * 4, ar[j]);
                split_store(nBhi, nBlo, sidx + j * 4, wr[j]);
            }
            if (k + 2 < NCHUNK) {
                #pragma unroll
                for (int j = 0; j < 4; j++) {
                    ar[j] = *(const float4*)(Ap + (k + 2) * PBK + j * 4);
                    wr[j] = *(const float4*)(Wp + (k + 2) * PBK + j * 4);
                }
            }
        }

        // MMAs on current buffer
        __nv_bfloat16* Ahi = reinterpret_cast<__nv_bfloat16*>(cur);
        __nv_bfloat16* Alo = Ahi + PBM * PP;
        __nv_bfloat16* Bhi = Alo + PBM * PP;
        __nv_bfloat16* Blo = Bhi + PBM * PP;
        #pragma unroll
        for (int ks = 0; ks < PBK; ks += 16) {
            FragA a_hi[2], a_lo[2];
            #pragma unroll
            for (int mt = 0; mt < 2; mt++) {
                int arow = (warp_m * 32 + mt * 16) * PP + ks;
                wmma::load_matrix_sync(a_hi[mt], Ahi + arow, PP);
                wmma::load_matrix_sync(a_lo[mt], Alo + arow, PP);
            }
            #pragma unroll
            for (int nt = 0; nt < 4; nt++) {
                FragBc b_hi, b_lo;
                int brow = (warp_n * 64 + nt * 16) * PP + ks;
                wmma::load_matrix_sync(b_hi, Bhi + brow, PP);
                wmma::load_matrix_sync(b_lo, Blo + brow, PP);
                #pragma unroll
                for (int mt = 0; mt < 2; mt++) {
                    wmma::mma_sync(acc[mt][nt], a_hi[mt], b_hi, acc[mt][nt]);
                    wmma::mma_sync(acc[mt][nt], a_hi[mt], b_lo, acc[mt][nt]);
                    wmma::mma_sync(acc[mt][nt], a_lo[mt], b_hi, acc[mt][nt]);
                }
            }
        }
        __syncthreads();
    }
}

// Kernel 1: fused QKV projection -> head-split layout [B, H, S, dk]
__global__ void __launch_bounds__(256, 2)
qkv_proj_kernel(const float* __restrict__ q, const float* __restrict__ k_,
                const float* __restrict__ v,
                const float* __restrict__ Wq, const float* __restrict__ bq,
                const float* __restrict__ Wk, const float* __restrict__ bk,
                const float* __restrict__ Wv, const float* __restrict__ bv)
{
    extern __shared__ __align__(16) unsigned char psm[];
    const float* A; const float* W; const float* bias; float* O;
    int z = blockIdx.z;
    if (z == 0)      { A = q;  W = Wq; bias = bq; O = g_Q; }
    else if (z == 1) { A = k_; W = Wk; bias = bk; O = g_K; }
    else             { A = v;  W = Wv; bias = bv; O = g_V; }

    int m0 = blockIdx.y * PBM;
    int n0 = blockIdx.x * 128;
    FragC acc[2][4];
    proj_gemm_core(A, W, bias, m0, n0, psm, acc);

    int wid = threadIdx.x >> 5;
    int warp_m = wid & 3, warp_n = wid >> 2;
    #pragma unroll
    for (int mt = 0; mt < 2; mt++) {
        int row0 = m0 + warp_m * 32 + mt * 16;
        int b = row0 >> 11;
        int s0 = row0 & 2047;
        #pragma unroll
        for (int nt = 0; nt < 4; nt++) {
            int n = n0 + warp_n * 64 + nt * 16;
            int h = n >> 6, off = n & 63;
            float* dst = O + ((size_t)(b * NHEAD + h) * S_LEN + s0) * DKH + off;
            wmma::store_matrix_sync(dst, acc[mt][nt], DKH, wmma::mem_row_major);
        }
    }
}

// ---------------------------------------------------------------------------
// Kernel 2: tensor-core flash attention, pipelined.
// grid = (16 q-tiles, 64 b*h), 256 threads (8 warps); BQ=128, BKV=64.
// Separate S/P/V storage + double-buffered K; per chunk:
//   [softmax_c, write P, rescale O, store V_c + K_{c+1}]  bar
//   [PV_c MMA + S_{c+1} MMA + gmem prefetch]              bar
// Smem 198656 B (1 CTA/SM).
// ---------------------------------------------------------------------------
#define BQ  128
#define BKV 64
#define BP  72     // bf16 pitch
#define FP  68     // fp32 pitch
#define Q_PLANE  (BQ * BP)    // 9216
#define KV_PLANE (BKV * BP)   // 4608
#define O_ELEMS  (BQ * FP)    // 8704
#define ATTN_SMEM ((4*Q_PLANE + 6*KV_PLANE) * 2 + 2 * O_ELEMS * 4)  // 198656

__device__ __forceinline__ void s_mma(int wid,
    const __nv_bfloat16* Qhi, const __nv_bfloat16* Qlo,
    const __nv_bfloat16* Khi, const __nv_bfloat16* Klo, float* Ssm)
{
    FragC sf[4];
    #pragma unroll
    for (int nt = 0; nt < 4; nt++) wmma::fill_fragment(sf[nt], 0.0f);
    #pragma unroll
    for (int ks = 0; ks < 4; ks++) {
        FragA ah, al;
        wmma::load_matrix_sync(ah, Qhi + (wid * 16) * BP + ks * 16, BP);
        wmma::load_matrix_sync(al, Qlo + (wid * 16) * BP + ks * 16, BP);
        #pragma unroll
        for (int nt = 0; nt < 4; nt++) {
            FragBc bh_, bl_;
            wmma::load_matrix_sync(bh_, Khi + (nt * 16) * BP + ks * 16, BP);
            wmma::load_matrix_sync(bl_, Klo + (nt * 16) * BP + ks * 16, BP);
            wmma::mma_sync(sf[nt], ah, bh_, sf[nt]);
            wmma::mma_sync(sf[nt], ah, bl_, sf[nt]);
            wmma::mma_sync(sf[nt], al, bh_, sf[nt]);
        }
    }
    #pragma unroll
    for (int nt = 0; nt < 4; nt++)
        wmma::store_matrix_sync(Ssm + (wid * 16) * FP + nt * 16, sf[nt],
                                FP, wmma::mem_row_major);
}

__device__ __forceinline__ void pv_mma(int wid,
    const __nv_bfloat16* Phi, const __nv_bfloat16* Plo,
    const __nv_bfloat16* Vhi, const __nv_bfloat16* Vlo, float* Osm)
{
    FragC of[4];
    #pragma unroll
    for (int nt = 0; nt < 4; nt++)
        wmma::load_matrix_sync(of[nt], Osm + (wid * 16) * FP + nt * 16,
                               FP, wmma::mem_row_major);
    #pragma unroll
    for (int ks = 0; ks < 4; ks++) {
        FragA ph_, pl_;
        wmma::load_matrix_sync(ph_, Phi + (wid * 16) * BP + ks * 16, BP);
        wmma::load_matrix_sync(pl_, Plo + (wid * 16) * BP + ks * 16, BP);
        #pragma unroll
        for (int nt = 0; nt < 4; nt++) {
            FragBr vh_, vl_;
            wmma::load_matrix_sync(vh_, Vhi + (ks * 16) * BP + nt * 16, BP);
            wmma::load_matrix_sync(vl_, Vlo + (ks * 16) * BP + nt * 16, BP);
            wmma::mma_sync(of[nt], ph_, vh_, of[nt]);
            wmma::mma_sync(of[nt], ph_, vl_, of[nt]);
            wmma::mma_sync(of[nt], pl_, vh_, of[nt]);
        }
    }
    #pragma unroll
    for (int nt = 0; nt < 4; nt++)
        wmma::store_matrix_sync(Osm + (wid * 16) * FP + nt * 16, of[nt],
                                FP, wmma::mem_row_major);
}

__global__ void __launch_bounds__(256)
attn_kernel()
{
    extern __shared__ __align__(16) unsigned char smraw[];
    __nv_bfloat16* Qhi  = reinterpret_cast<__nv_bfloat16*>(smraw);
    __nv_bfloat16* Qlo  = Qhi + Q_PLANE;
    __nv_bfloat16* Khi0 = Qlo + Q_PLANE;
    __nv_bfloat16* Klo0 = Khi0 + KV_PLANE;
    __nv_bfloat16* Khi1 = Klo0 + KV_PLANE;
    __nv_bfloat16* Klo1 = Khi1 + KV_PLANE;
    __nv_bfloat16* Vhi  = Klo1 + KV_PLANE;
    __nv_bfloat16* Vlo  = Vhi + KV_PLANE;
    __nv_bfloat16* Phi  = Vlo + KV_PLANE;
    __nv_bfloat16* Plo  = Phi + Q_PLANE;
    float* Osm = reinterpret_cast<float*>(Plo + Q_PLANE);
    float* Ssm = Osm + O_ELEMS;

    int tid = threadIdx.x;
    int wid = tid >> 5;
    int bh = blockIdx.y;
    int q0 = blockIdx.x * BQ;
    const float* Qb = g_Q + (size_t)bh * S_LEN * DKH;
    const float* Kb = g_K + (size_t)bh * S_LEN * DKH;
    const float* Vb = g_V + (size_t)bh * S_LEN * DKH;

    const int r  = tid >> 1;            // softmax row
    const int c0 = (tid & 1) * 32;      // column half
    const int lr  = tid >> 2;           // kv loader row
    const int lc0 = (tid & 3) << 4;     // kv loader col base

    // Prologue: K_0 regs, then store Q + K_0 + zero O
    float4 kreg[4];
    #pragma unroll
    for (int j = 0; j < 4; j++)
        kreg[j] = *(const float4*)(Kb + (size_t)lr * DKH + lc0 + j * 4);
    #pragma unroll
    for (int j = 0; j < 8; j++) {
        float4 t = *(const float4*)(Qb + (size_t)(q0 + r) * DKH + c0 + j * 4);
        split_store(Qhi, Qlo, r * BP + c0 + j * 4, t);
    }
    #pragma unroll
    for (int j = 0; j < 4; j++)
        split_store(Khi0, Klo0, lr * BP + lc0 + j * 4, kreg[j]);
    for (int i = tid; i < O_ELEMS; i += 256) Osm[i] = 0.f;
    __syncthreads();

    // S_0 ; prefetch V_0, K_1
    float4 vreg[4];
    #pragma unroll
    for (int j = 0; j < 4; j++)
        vreg[j] = *(const float4*)(Vb + (size_t)lr * DKH + lc0 + j * 4);
    #pragma unroll
    for (int j = 0; j < 4; j++)
        kreg[j] = *(const float4*)(Kb + (size_t)(BKV + lr) * DKH + lc0 + j * 4);
    s_mma(wid, Qhi, Qlo, Khi0, Klo0, Ssm);
    __syncthreads();

    float m_run = -INFINITY, l_run = 0.f;
    const float SCALE = 0.125f;
    const int NC = S_LEN / BKV;   // 32

    for (int c = 0; c < NC; c++) {
        // ---- Phase A: softmax + P write + O rescale + V_c / K_{c+1} stores ----
        float p[32], corr;
        {
            float s[32];
            #pragma unroll
            for (int j = 0; j < 8; j++) {
                float4 t = *(const float4*)&Ssm[r * FP + c0 + j * 4];
                s[j*4+0] = t.x * SCALE; s[j*4+1] = t.y * SCALE;
                s[j*4+2] = t.z * SCALE; s[j*4+3] = t.w * SCALE;
            }
            float mc = s[0];
            #pragma unroll
            for (int j = 1; j < 32; j++) mc = fmaxf(mc, s[j]);
            mc = fmaxf(mc, __shfl_xor_sync(0xffffffffu, mc, 1));
            float mnew = fmaxf(m_run, mc);
            corr = __expf(m_run - mnew);
            m_run = mnew;
            float ps = 0.f;
            #pragma unroll
            for (int j = 0; j < 32; j++) { p[j] = __expf(s[j] - mnew); ps += p[j]; }
            ps += __shfl_xor_sync(0xffffffffu, ps, 1);
            l_run = l_run * corr + ps;
        }
        {
            __nv_bfloat16 hb[32], lb[32];
            #pragma unroll
            for (int j = 0; j < 32; j++) {
                hb[j] = __float2bfloat16_rn(p[j]);
                lb[j] = __float2bfloat16_rn(p[j] - __bfloat162float(hb[j]));
            }
            float4* Ph4 = reinterpret_cast<float4*>(Phi + r * BP + c0);
            float4* Pl4 = reinterpret_cast<float4*>(Plo + r * BP + c0);
            const float4* hb4 = reinterpret_cast<const float4*>(hb);
            const float4* lb4 = reinterpret_cast<const float4*>(lb);
            #pragma unroll
            for (int j = 0; j < 4; j++) { Ph4[j] = hb4[j]; Pl4[j] = lb4[j]; }
            #pragma unroll
            for (int j = 0; j < 8; j++) {
                float4* o4 = reinterpret_cast<float4*>(&Osm[r * FP + c0 + j * 4]);
                float4 t = *o4;
                t.x *= corr; t.y *= corr; t.z *= corr; t.w *= corr;
                *o4 = t;
            }
            #pragma unroll
            for (int j = 0; j < 4; j++)
                split_store(Vhi, Vlo, lr * BP + lc0 + j * 4, vreg[j]);
            if (c + 1 < NC) {
                __nv_bfloat16* nkh = ((c + 1) & 1) ? Khi1 : Khi0;
                __nv_bfloat16* nkl = ((c + 1) & 1) ? Klo1 : Klo0;
                #pragma unroll
                for (int j = 0; j < 4; j++)
                    split_store(nkh, nkl, lr * BP + lc0 + j * 4, kreg[j]);
            }
        }
        __syncthreads();

        // ---- Phase B: gmem prefetch + PV_c + S_{c+1} ----
        if (c + 1 < NC) {
            #pragma unroll
            for (int j = 0; j < 4; j++)
                vreg[j] = *(const float4*)(Vb + (size_t)((c + 1) * BKV + lr) * DKH + lc0 + j * 4);
        }
        if (c + 2 < NC) {
            #pragma unroll
            for (int j = 0; j < 4; j++)
                kreg[j] = *(const float4*)(Kb + (size_t)((c + 2) * BKV + lr) * DKH + lc0 + j * 4);
        }
        pv_mma(wid, Phi, Plo, Vhi, Vlo, Osm);
        if (c + 1 < NC) {
            __nv_bfloat16* ckh = ((c + 1) & 1) ? Khi1 : Khi0;
            __nv_bfloat16* ckl = ((c + 1) & 1) ? Klo1 : Klo0;
            s_mma(wid, Qhi, Qlo, ckh, ckl, Ssm);
        }
        __syncthreads();
    }

    // Normalize own row slice, store to merged-head layout [B, S, H*dk]
    int b = bh >> 4, h = bh & 15;
    float inv = 1.0f / l_run;
    int s = q0 + r;
    float* dst = g_ctx + (size_t)(b * S_LEN + s) * D_MODEL + h * DKH + c0;
    #pragma unroll
    for (int j = 0; j < 8; j++) {
        float4 t = *(const float4*)&Osm[r * FP + c0 + j * 4];
        t.x *= inv; t.y *= inv; t.z *= inv; t.w *= inv;
        *(float4*)(dst + j * 4) = t;
    }
}

// ---------------------------------------------------------------------------
// Kernel 3: output projection  out = ctx @ Wo^T + bo
// ---------------------------------------------------------------------------
__global__ void __launch_bounds__(256, 2)
out_proj_kernel(const float* __restrict__ Wo, const float* __restrict__ bo,
                float* __restrict__ out)
{
    extern __shared__ __align__(16) unsigned char psm[];
    int m0 = blockIdx.y * PBM;
    int n0 = blockIdx.x * 128;
    FragC acc[2][4];
    proj_gemm_core(g_ctx, Wo, bo, m0, n0, psm, acc);

    int wid = threadIdx.x >> 5;
    int warp_m = wid & 3, warp_n = wid >> 2;
    #pragma unroll
    for (int mt = 0; mt < 2; mt++) {
        int row0 = m0 + warp_m * 32 + mt * 16;
        #pragma unroll
        for (int nt = 0; nt < 4; nt++) {
            int n = n0 + warp_n * 64 + nt * 16;
            wmma::store_matrix_sync(out + (size_t)row0 * D_MODEL + n,
                                    acc[mt][nt], D_MODEL, wmma::mem_row_major);
        }
    }
}

// ---------------------------------------------------------------------------
// Launch. Input order (metadata): q,k,v,Wq,bq,Wk,bk,Wv,bv,Wo,bo
// ---------------------------------------------------------------------------
extern "C" void kernel_launch(void* const* d_in, const int* in_sizes, int n_in,
                              void* d_out, int out_size)
{
    const float* q  = (const float*)d_in[0];
    const float* k  = (const float*)d_in[1];
    const float* v  = (const float*)d_in[2];
    const float* Wq = (const float*)d_in[3];
    const float* bq = (const float*)d_in[4];
    const float* Wk = (const float*)d_in[5];
    const float* bk = (const float*)d_in[6];
    const float* Wv = (const float*)d_in[7];
    const float* bv = (const float*)d_in[8];
    const float* Wo = (const float*)d_in[9];
    const float* bo = (const float*)d_in[10];
    float* out = (float*)d_out;

    // Idempotent, host-side, capture-safe smem opt-ins
    cudaFuncSetAttribute(attn_kernel,
                         cudaFuncAttributeMaxDynamicSharedMemorySize, ATTN_SMEM);
    cudaFuncSetAttribute(qkv_proj_kernel,
                         cudaFuncAttributeMaxDynamicSharedMemorySize, PSM_BYTES);
    cudaFuncSetAttribute(out_proj_kernel,
                         cudaFuncAttributeMaxDynamicSharedMemorySize, PSM_BYTES);

    dim3 blk(256);
    qkv_proj_kernel<<<dim3(D_MODEL / 128, ROWS / PBM, 3), blk, PSM_BYTES>>>(
        q, k, v, Wq, bq, Wk, bk, Wv, bv);
    attn_kernel<<<dim3(S_LEN / BQ, BATCH * NHEAD), blk, ATTN_SMEM>>>();
    out_proj_kernel<<<dim3(D_MODEL / 128, ROWS / PBM), blk, PSM_BYTES>>>(Wo, bo, out);
}

// round 14
// speedup vs baseline: 1.1463x; 1.1463x over previous
#include <cuda_runtime.h>
#include <cuda_bf16.h>
#include <mma.h>
#include <math.h>

using namespace nvcuda;

// Problem constants
#define D_MODEL 1024
#define NHEAD   16
#define DKH     64
#define S_LEN   2048
#define BATCH   4
#define ROWS    (BATCH * S_LEN)   // 8192

// Scratch (static device globals: allocation-free per harness rules)
__device__ float g_Q[ROWS * D_MODEL];
__device__ float g_K[ROWS * D_MODEL];
__device__ float g_V[ROWS * D_MODEL];
__device__ float g_ctx[ROWS * D_MODEL];

// ---------------------------------------------------------------------------
// fp32 -> (bf16 hi, bf16 lo) split helpers
// ---------------------------------------------------------------------------
__device__ __forceinline__ void split_store(__nv_bfloat16* hi, __nv_bfloat16* lo,
                                            int idx, float4 v)
{
    float f[4] = {v.x, v.y, v.z, v.w};
    __nv_bfloat16 h[4], l[4];
    #pragma unroll
    for (int e = 0; e < 4; e++) {
        h[e] = __float2bfloat16_rn(f[e]);
        l[e] = __float2bfloat16_rn(f[e] - __bfloat162float(h[e]));
    }
    *reinterpret_cast<__nv_bfloat162*>(hi + idx)     = __nv_bfloat162(h[0], h[1]);
    *reinterpret_cast<__nv_bfloat162*>(hi + idx + 2) = __nv_bfloat162(h[2], h[3]);
    *reinterpret_cast<__nv_bfloat162*>(lo + idx)     = __nv_bfloat162(l[0], l[1]);
    *reinterpret_cast<__nv_bfloat162*>(lo + idx + 2) = __nv_bfloat162(l[2], l[3]);
}

typedef wmma::fragment<wmma::matrix_a, 16,16,16, __nv_bfloat16, wmma::row_major> FragA;
typedef wmma::fragment<wmma::matrix_b, 16,16,16, __nv_bfloat16, wmma::col_major> FragBc;
typedef wmma::fragment<wmma::matrix_b, 16,16,16, __nv_bfloat16, wmma::row_major> FragBr;
typedef wmma::fragment<wmma::accumulator, 16,16,16, float> FragC;

// ---------------------------------------------------------------------------
// Projection GEMM, double-buffered (R12, measured 720us qkv):
// C = A @ W^T + bias. CTA 128x128, K-chunk 32, 8 warps; 1 barrier/chunk.
// ---------------------------------------------------------------------------
#define PBM 128
#define PBK 32
#define PP  40
#define PLANE_BYTES (PBM * PP * 2)       // 10240
#define BUF_BYTES   (4 * PLANE_BYTES)    // 40960
#define PSM_BYTES   (2 * BUF_BYTES)      // 81920 dynamic

__device__ __forceinline__ void proj_gemm_core(
    const float* __restrict__ A, const float* __restrict__ W,
    const float* __restrict__ bias, int m0, int n0,
    unsigned char* smem_raw, FragC (&acc)[2][4])
{
    const int K = D_MODEL;
    int tid = threadIdx.x;
    int wid = tid >> 5;
    int warp_m = wid & 3;
    int warp_n = wid >> 2;

    int lrow = tid >> 1;
    int lkh  = (tid & 1) * 16;
    const float* Ap = A + (size_t)(m0 + lrow) * K + lkh;
    const float* Wp = W + (size_t)(n0 + lrow) * K + lkh;

    float* btile = reinterpret_cast<float*>(smem_raw + BUF_BYTES);  // unions buf1

    float4 ar[4], wr[4];
    #pragma unroll
    for (int j = 0; j < 4; j++) {
        ar[j] = *(const float4*)(Ap + j * 4);
        wr[j] = *(const float4*)(Wp + j * 4);
    }

    for (int idx = tid; idx < 16 * 128; idx += 256) {
        int r = idx >> 7, c = idx & 127;
        btile[r * 136 + c] = bias[n0 + c];
    }
    {
        __nv_bfloat16* Ahi = reinterpret_cast<__nv_bfloat16*>(smem_raw);
        __nv_bfloat16* Alo = Ahi + PBM * PP;
        __nv_bfloat16* Bhi = Alo + PBM * PP;
        __nv_bfloat16* Blo = Bhi + PBM * PP;
        int sidx = lrow * PP + lkh;
        #pragma unroll
        for (int j = 0; j < 4; j++) {
            split_store(Ahi, Alo, sidx + j * 4, ar[j]);
            split_store(Bhi, Blo, sidx + j * 4, wr[j]);
        }
    }
    __syncthreads();

    #pragma unroll
    for (int mt = 0; mt < 2; mt++)
        #pragma unroll
        for (int nt = 0; nt < 4; nt++)
            wmma::load_matrix_sync(acc[mt][nt],
                btile + warp_n * 64 + nt * 16, 136, wmma::mem_row_major);

    #pragma unroll
    for (int j = 0; j < 4; j++) {
        ar[j] = *(const float4*)(Ap + PBK + j * 4);
        wr[j] = *(const float4*)(Wp + PBK + j * 4);
    }
    __syncthreads();   // acc-frag loads done before buf1 (btile) is overwritten

    const int NCHUNK = K / PBK;   // 32
    for (int k = 0; k < NCHUNK; k++) {
        unsigned char* cur = smem_raw + (k & 1) * BUF_BYTES;
        unsigned char* nxt = smem_raw + ((k + 1) & 1) * BUF_BYTES;

        if (k + 1 < NCHUNK) {
            __nv_bfloat16* nAhi = reinterpret_cast<__nv_bfloat16*>(nxt);
            __nv_bfloat16* nAlo = nAhi + PBM * PP;
            __nv_bfloat16* nBhi = nAlo + PBM * PP;
            __nv_bfloat16* nBlo = nBhi + PBM * PP;
            int sidx = lrow * PP + lkh;
            #pragma unroll
            for (int j = 0; j < 4; j++) {
                split_store(nAhi, nAlo, sidx + j * 4, ar[j]);
                split_store(nBhi, nBlo, sidx + j * 4, wr[j]);
            }
            if (k + 2 < NCHUNK) {
                #pragma unroll
                for (int j = 0; j < 4; j++) {
                    ar[j] = *(const float4*)(Ap + (k + 2) * PBK + j * 4);
                    wr[j] = *(const float4*)(Wp + (k + 2) * PBK + j * 4);
                }
            }
        }

        __nv_bfloat16* Ahi = reinterpret_cast<__nv_bfloat16*>(cur);
        __nv_bfloat16* Alo = Ahi + PBM * PP;
        __nv_bfloat16* Bhi = Alo + PBM * PP;
        __nv_bfloat16* Blo = Bhi + PBM * PP;
        #pragma unroll
        for (int ks = 0; ks < PBK; ks += 16) {
            FragA a_hi[2], a_lo[2];
            #pragma unroll
            for (int mt = 0; mt < 2; mt++) {
                int arow = (warp_m * 32 + mt * 16) * PP + ks;
                wmma::load_matrix_sync(a_hi[mt], Ahi + arow, PP);
                wmma::load_matrix_sync(a_lo[mt], Alo + arow, PP);
            }
            #pragma unroll
            for (int nt = 0; nt < 4; nt++) {
                FragBc b_hi, b_lo;
                int brow = (warp_n * 64 + nt * 16) * PP + ks;
                wmma::load_matrix_sync(b_hi, Bhi + brow, PP);
                wmma::load_matrix_sync(b_lo, Blo + brow, PP);
                #pragma unroll
                for (int mt = 0; mt < 2; mt++) {
                    wmma::mma_sync(acc[mt][nt], a_hi[mt], b_hi, acc[mt][nt]);
                    wmma::mma_sync(acc[mt][nt], a_hi[mt], b_lo, acc[mt][nt]);
                    wmma::mma_sync(acc[mt][nt], a_lo[mt], b_hi, acc[mt][nt]);
                }
            }
        }
        __syncthreads();
    }
}

// Kernel 1: fused QKV projection -> head-split layout [B, H, S, dk]
__global__ void __launch_bounds__(256, 2)
qkv_proj_kernel(const float* __restrict__ q, const float* __restrict__ k_,
                const float* __restrict__ v,
                const float* __restrict__ Wq, const float* __restrict__ bq,
                const float* __restrict__ Wk, const float* __restrict__ bk,
                const float* __restrict__ Wv, const float* __restrict__ bv)
{
    extern __shared__ __align__(16) unsigned char psm[];
    const float* A; const float* W; const float* bias; float* O;
    int z = blockIdx.z;
    if (z == 0)      { A = q;  W = Wq; bias = bq; O = g_Q; }
    else if (z == 1) { A = k_; W = Wk; bias = bk; O = g_K; }
    else             { A = v;  W = Wv; bias = bv; O = g_V; }

    int m0 = blockIdx.y * PBM;
    int n0 = blockIdx.x * 128;
    FragC acc[2][4];
    proj_gemm_core(A, W, bias, m0, n0, psm, acc);

    int wid = threadIdx.x >> 5;
    int warp_m = wid & 3, warp_n = wid >> 2;
    #pragma unroll
    for (int mt = 0; mt < 2; mt++) {
        int row0 = m0 + warp_m * 32 + mt * 16;
        int b = row0 >> 11;
        int s0 = row0 & 2047;
        #pragma unroll
        for (int nt = 0; nt < 4; nt++) {
            int n = n0 + warp_n * 64 + nt * 16;
            int h = n >> 6, off = n & 63;
            float* dst = O + ((size_t)(b * NHEAD + h) * S_LEN + s0) * DKH + off;
            wmma::store_matrix_sync(dst, acc[mt][nt], DKH, wmma::mem_row_major);
        }
    }
}

// ---------------------------------------------------------------------------
// Kernel 2: tensor-core flash attention with PERSISTENT register O.
// grid = (16 q-tiles, 64 b*h), 256 threads (8 warps); BQ=128, BKV=64.
// Warp w's MMA rows (16w..16w+15) == its softmax threads' rows, so a
// TILE-WIDE max (warp-reduced) makes corr warp-uniform -> FragC O can be
// rescaled element-wise in registers. O never touches smem until epilogue.
// Smem 92160 B: Q hi/lo, K/V hi/lo (shared planes), union{S fp32, P hi/lo}.
// ---------------------------------------------------------------------------
#define BQ  128
#define BKV 64
#define BP  72
#define FP  68
#define Q_PLANE  (BQ * BP)    // 9216
#define KV_PLANE (BKV * BP)   // 4608
#define UNION_B  36864        // max(128*68*4, 2*9216*2)
#define ATTN_SMEM ((2*Q_PLANE + 2*KV_PLANE) * 2 + UNION_B)   // 92160

__global__ void __launch_bounds__(256)
attn_kernel()
{
    extern __shared__ __align__(16) unsigned char smraw[];
    __nv_bfloat16* Qhi = reinterpret_cast<__nv_bfloat16*>(smraw);
    __nv_bfloat16* Qlo = Qhi + Q_PLANE;
    __nv_bfloat16* Khi = Qlo + Q_PLANE;
    __nv_bfloat16* Klo = Khi + KV_PLANE;
    unsigned char* uni = reinterpret_cast<unsigned char*>(Klo + KV_PLANE);
    float* Ssm = reinterpret_cast<float*>(uni);
    __nv_bfloat16* Phi = reinterpret_cast<__nv_bfloat16*>(uni);
    __nv_bfloat16* Plo = Phi + Q_PLANE;

    int tid = threadIdx.x;
    int wid = tid >> 5;
    int bh = blockIdx.y;
    int q0 = blockIdx.x * BQ;
    const float* Qb = g_Q + (size_t)bh * S_LEN * DKH;
    const float* Kb = g_K + (size_t)bh * S_LEN * DKH;
    const float* Vb = g_V + (size_t)bh * S_LEN * DKH;

    const int r  = tid >> 1;            // softmax row (== own warp's MMA rows)
    const int c0 = (tid & 1) * 32;      // column half

    // Load + split Q tile once
    #pragma unroll
    for (int j = 0; j < 8; j++) {
        float4 t = *(const float4*)(Qb + (size_t)(q0 + r) * DKH + c0 + j * 4);
        split_store(Qhi, Qlo, r * BP + c0 + j * 4, t);
    }

    // Persistent O accumulators (registers)
    FragC of[4];
    #pragma unroll
    for (int nt = 0; nt < 4; nt++) wmma::fill_fragment(of[nt], 0.0f);

    float m_run = -INFINITY;   // warp-uniform tile max
    float l_run = 0.f;         // per-row (thread-local)

    const int lr  = tid >> 2;
    const int lc0 = (tid & 3) << 4;
    float4 kreg[4];
    #pragma unroll
    for (int j = 0; j < 4; j++)
        kreg[j] = *(const float4*)(Kb + (size_t)lr * DKH + lc0 + j * 4);

    const float SCALE = 0.125f;   // 1/sqrt(64)

    for (int c = 0; c < S_LEN / BKV; c++) {
        __syncthreads();               // (1) prev PV done with P and V planes
        #pragma unroll
        for (int j = 0; j < 4; j++)
            split_store(Khi, Klo, lr * BP + lc0 + j * 4, kreg[j]);
        __syncthreads();               // (2) K planes ready

        float4 vreg[4];
        #pragma unroll
        for (int j = 0; j < 4; j++)
            vreg[j] = *(const float4*)(Vb + (size_t)(c * BKV + lr) * DKH + lc0 + j * 4);

        // ---- S = Q K^T ----
        {
            FragC sf[4];
            #pragma unroll
            for (int nt = 0; nt < 4; nt++) wmma::fill_fragment(sf[nt], 0.0f);
            #pragma unroll
            for (int ks = 0; ks < 4; ks++) {
                FragA ah, al;
                wmma::load_matrix_sync(ah, Qhi + (wid * 16) * BP + ks * 16, BP);
                wmma::load_matrix_sync(al, Qlo + (wid * 16) * BP + ks * 16, BP);
                #pragma unroll
                for (int nt = 0; nt < 4; nt++) {
                    FragBc bh_, bl_;
                    wmma::load_matrix_sync(bh_, Khi + (nt * 16) * BP + ks * 16, BP);
                    wmma::load_matrix_sync(bl_, Klo + (nt * 16) * BP + ks * 16, BP);
                    wmma::mma_sync(sf[nt], ah, bh_, sf[nt]);
                    wmma::mma_sync(sf[nt], ah, bl_, sf[nt]);
                    wmma::mma_sync(sf[nt], al, bh_, sf[nt]);
                }
            }
            #pragma unroll
            for (int nt = 0; nt < 4; nt++)
                wmma::store_matrix_sync(Ssm + (wid * 16) * FP + nt * 16, sf[nt],
                                        FP, wmma::mem_row_major);
        }
        __syncthreads();               // (3) S ready

        if (c + 1 < S_LEN / BKV) {
            #pragma unroll
            for (int j = 0; j < 4; j++)
                kreg[j] = *(const float4*)(Kb + (size_t)((c + 1) * BKV + lr) * DKH + lc0 + j * 4);
        }

        // ---- Softmax with warp-uniform (tile-wide) max ----
        float p[32], corr;
        {
            float s[32];
            #pragma unroll
            for (int j = 0; j < 8; j++) {
                float4 t = *(const float4*)&Ssm[r * FP + c0 + j * 4];
                s[j*4+0] = t.x * SCALE; s[j*4+1] = t.y * SCALE;
                s[j*4+2] = t.z * SCALE; s[j*4+3] = t.w * SCALE;
            }
            float mc = s[0];
            #pragma unroll
            for (int j = 1; j < 32; j++) mc = fmaxf(mc, s[j]);
            // Warp-wide max: covers all 16 rows x 64 cols of this warp's tile
            #pragma unroll
            for (int o = 16; o > 0; o >>= 1)
                mc = fmaxf(mc, __shfl_xor_sync(0xffffffffu, mc, o));
            float mnew = fmaxf(m_run, mc);
            corr = __expf(m_run - mnew);    // warp-uniform
            m_run = mnew;
            float ps = 0.f;
            #pragma unroll
            for (int j = 0; j < 32; j++) { p[j] = __expf(s[j] - mnew); ps += p[j]; }
            ps += __shfl_xor_sync(0xffffffffu, ps, 1);   // row partner
            l_run = l_run * corr + ps;      // per-row, corr uniform
        }
        __syncthreads();               // (4) S reads done; P may overwrite

        // ---- Write P hi/lo; store V into shared K planes ----
        {
            __nv_bfloat16 hb[32], lb[32];
            #pragma unroll
            for (int j = 0; j < 32; j++) {
                hb[j] = __float2bfloat16_rn(p[j]);
                lb[j] = __float2bfloat16_rn(p[j] - __bfloat162float(hb[j]));
            }
            float4* Ph4 = reinterpret_cast<float4*>(Phi + r * BP + c0);
            float4* Pl4 = reinterpret_cast<float4*>(Plo + r * BP + c0);
            const float4* hb4 = reinterpret_cast<const float4*>(hb);
            const float4* lb4 = reinterpret_cast<const float4*>(lb);
            #pragma unroll
            for (int j = 0; j < 4; j++) { Ph4[j] = hb4[j]; Pl4[j] = lb4[j]; }
            #pragma unroll
            for (int j = 0; j < 4; j++)
                split_store(Khi, Klo, lr * BP + lc0 + j * 4, vreg[j]);
        }
        __syncthreads();               // (5) P + V planes ready

        // ---- O = O*corr + P V  (O stays in registers) ----
        #pragma unroll
        for (int nt = 0; nt < 4; nt++)
            #pragma unroll
            for (int i = 0; i < of[nt].num_elements; i++)
                of[nt].x[i] *= corr;
        #pragma unroll
        for (int ks = 0; ks < 4; ks++) {
            FragA ph_, pl_;
            wmma::load_matrix_sync(ph_, Phi + (wid * 16) * BP + ks * 16, BP);
            wmma::load_matrix_sync(pl_, Plo + (wid * 16) * BP + ks * 16, BP);
            #pragma unroll
            for (int nt = 0; nt < 4; nt++) {
                FragBr vh_, vl_;
                wmma::load_matrix_sync(vh_, Khi + (ks * 16) * BP + nt * 16, BP);
                wmma::load_matrix_sync(vl_, Klo + (ks * 16) * BP + nt * 16, BP);
                wmma::mma_sync(of[nt], ph_, vh_, of[nt]);
                wmma::mma_sync(of[nt], ph_, vl_, of[nt]);
                wmma::mma_sync(of[nt], pl_, vh_, of[nt]);
            }
        }
    }

    // Epilogue: stage O through Ssm once, normalize per row, store.
    __syncthreads();
    #pragma unroll
    for (int nt = 0; nt < 4; nt++)
        wmma::store_matrix_sync(Ssm + (wid * 16) * FP + nt * 16, of[nt],
                                FP, wmma::mem_row_major);
    __syncthreads();

    int b = bh >> 4, h = bh & 15;
    float inv = 1.0f / l_run;
    int s = q0 + r;
    float* dst = g_ctx + (size_t)(b * S_LEN + s) * D_MODEL + h * DKH + c0;
    #pragma unroll
    for (int j = 0; j < 8; j++) {
        float4 t = *(const float4*)&Ssm[r * FP + c0 + j * 4];
        t.x *= inv; t.y *= inv; t.z *= inv; t.w *= inv;
        *(float4*)(dst + j * 4) = t;
    }
}

// ---------------------------------------------------------------------------
// Kernel 3: output projection  out = ctx @ Wo^T + bo
// ---------------------------------------------------------------------------
__global__ void __launch_bounds__(256, 2)
out_proj_kernel(const float* __restrict__ Wo, const float* __restrict__ bo,
                float* __restrict__ out)
{
    extern __shared__ __align__(16) unsigned char psm[];
    int m0 = blockIdx.y * PBM;
    int n0 = blockIdx.x * 128;
    FragC acc[2][4];
    proj_gemm_core(g_ctx, Wo, bo, m0, n0, psm, acc);

    int wid = threadIdx.x >> 5;
    int warp_m = wid & 3, warp_n = wid >> 2;
    #pragma unroll
    for (int mt = 0; mt < 2; mt++) {
        int row0 = m0 + warp_m * 32 + mt * 16;
        #pragma unroll
        for (int nt = 0; nt < 4; nt++) {
            int n = n0 + warp_n * 64 + nt * 16;
            wmma::store_matrix_sync(out + (size_t)row0 * D_MODEL + n,
                                    acc[mt][nt], D_MODEL, wmma::mem_row_major);
        }
    }
}

// ---------------------------------------------------------------------------
// Launch. Input order (metadata): q,k,v,Wq,bq,Wk,bk,Wv,bv,Wo,bo
// ---------------------------------------------------------------------------
extern "C" void kernel_launch(void* const* d_in, const int* in_sizes, int n_in,
                              void* d_out, int out_size)
{
    const float* q  = (const float*)d_in[0];
    const float* k  = (const float*)d_in[1];
    const float* v  = (const float*)d_in[2];
    const float* Wq = (const float*)d_in[3];
    const float* bq = (const float*)d_in[4];
    const float* Wk = (const float*)d_in[5];
    const float* bk = (const float*)d_in[6];
    const float* Wv = (const float*)d_in[7];
    const float* bv = (const float*)d_in[8];
    const float* Wo = (const float*)d_in[9];
    const float* bo = (const float*)d_in[10];
    float* out = (float*)d_out;

    // Idempotent, host-side, capture-safe smem opt-ins
    cudaFuncSetAttribute(attn_kernel,
                         cudaFuncAttributeMaxDynamicSharedMemorySize, ATTN_SMEM);
    cudaFuncSetAttribute(qkv_proj_kernel,
                         cudaFuncAttributeMaxDynamicSharedMemorySize, PSM_BYTES);
    cudaFuncSetAttribute(out_proj_kernel,
                         cudaFuncAttributeMaxDynamicSharedMemorySize, PSM_BYTES);

    dim3 blk(256);
    qkv_proj_kernel<<<dim3(D_MODEL / 128, ROWS / PBM, 3), blk, PSM_BYTES>>>(
        q, k, v, Wq, bq, Wk, bk, Wv, bv);
    attn_kernel<<<dim3(S_LEN / BQ, BATCH * NHEAD), blk, ATTN_SMEM>>>();
    out_proj_kernel<<<dim3(D_MODEL / 128, ROWS / PBM), blk, PSM_BYTES>>>(Wo, bo, out);
}